// round 5
// baseline (speedup 1.0000x reference)
#include <cuda_runtime.h>

// LSTM_46316927320185 — R5: two-phase (xproj GEMM + lean recurrence)
// B=4096, T=512, EMB=32, HID=16. out = sigmoid(h_T @ fc_w^T + fc_b), [B,1] fp32.
//
// R4 (447us): FMA busy only 50% — recurrence critical path (LDS/shfl/MUFU epi)
// exposed. 2/3 of in-loop FMA (input projection) has no recurrence dependency.
// Phase A: xp[t][b][j] = emb@w_ih^T + biases, all tokens, FMA-bound, fully
//   pipelined. fma2 packed over K-PAIRS: float4 LDS halves are (e_k,e_k+1)
//   packed operands -> zero rep2 movs. Weights loaded directly as u64 pairs
//   from gmem (aligned), no smem transpose.
// Phase B: recurrence with only h-projection (64 fma2/thread-step) + coalesced
//   xp stream (prefetched). Epilogue SPLIT across gp halves: 20 MUFU/thread.
// Scratch: 512MB __device__ global (allowed per harness rules).

#define HID    16
#define EMB    32
#define T_LEN  512
#define BATCH  4096

#define ELEMS_PER_CTA 32
#define CTA_THREADS   256
#define GRID_CTAS     (BATCH / ELEMS_PER_CTA)   // 128

typedef unsigned long long u64;

// [t][b][j] -> float4 (xp_i, xp_f, xp_g, xp_o), biases folded in. 512 MB.
__device__ float4 g_xproj[(size_t)T_LEN * BATCH * HID];

__device__ __forceinline__ u64 fma2(u64 a, u64 b, u64 c) {
    u64 d; asm("fma.rn.f32x2 %0, %1, %2, %3;" : "=l"(d) : "l"(a), "l"(b), "l"(c)); return d;
}
__device__ __forceinline__ u64 add2(u64 a, u64 b) {
    u64 d; asm("add.rn.f32x2 %0, %1, %2;" : "=l"(d) : "l"(a), "l"(b)); return d;
}
__device__ __forceinline__ void unpack2(u64 v, float& lo, float& hi) {
    asm("mov.b64 {%0, %1}, %2;" : "=f"(lo), "=f"(hi) : "l"(v));
}
__device__ __forceinline__ float sigf(float x) {
    return __fdividef(1.0f, 1.0f + __expf(-x));
}
__device__ __forceinline__ float tanhf_fast(float x) {
    return __fdividef(2.0f, 1.0f + __expf(-2.0f * x)) - 1.0f;
}

// ---------------- Phase A: input projection for all (b, t) ----------------
__global__ __launch_bounds__(CTA_THREADS, 1)
void xproj_kernel(const int*   __restrict__ x,
                  const float* __restrict__ embed,
                  const float* __restrict__ w_ih,
                  const float* __restrict__ b_ih,
                  const float* __restrict__ b_hh)
{
    __shared__ float4 emb_s4[ELEMS_PER_CTA * 8];   // [elem][chunk]

    const int tid  = threadIdx.x;
    const int warp = tid >> 5, lane = tid & 31;
    const int j    = lane & 15;          // hidden unit owned
    const int gp   = lane >> 4;          // K half: emb k in [gp*16, gp*16+16)
    const int we   = warp * 4;
    const int b0w  = blockIdx.x * ELEMS_PER_CTA + we;

    // w_ih rows are 32 consecutive floats -> load K-pairs directly as u64
    u64 wih[4][8];
    #pragma unroll
    for (int g = 0; g < 4; ++g) {
        const u64* wr = (const u64*)(w_ih + ((size_t)(g * HID + j) * EMB + gp * 16));
        #pragma unroll
        for (int kp = 0; kp < 8; ++kp) wih[g][kp] = wr[kp];
    }
    float bias[4];
    #pragma unroll
    for (int g = 0; g < 4; ++g) bias[g] = b_ih[g * HID + j] + b_hh[g * HID + j];

    const int pe = lane >> 3, chunk = lane & 7;    // emb gather: lane -> (elem, chunk)
    const int* xcol = x + (long)(b0w + pe) * T_LEN;

    float4 pre;
    { int idx = xcol[0]; pre = ((const float4*)(embed + (long)idx * EMB))[chunk]; }

    const ulonglong2* emb_u = (const ulonglong2*)emb_s4;

    for (int t = 0; t < T_LEN; ++t) {
        __syncwarp();
        emb_s4[(we + pe) * 8 + chunk] = pre;
        __syncwarp();
        if (t + 1 < T_LEN) {
            int idx = xcol[t + 1];
            pre = ((const float4*)(embed + (long)idx * EMB))[chunk];
        }

        u64 a[4][4];
        #pragma unroll
        for (int e = 0; e < 4; ++e)
            #pragma unroll
            for (int g = 0; g < 4; ++g) a[e][g] = 0ull;

        // this half's 16 emb values (4 chunks), K-pair packed
        #pragma unroll
        for (int e = 0; e < 4; ++e) {
            #pragma unroll
            for (int c4 = 0; c4 < 4; ++c4) {
                const ulonglong2 ev = emb_u[(we + e) * 8 + gp * 4 + c4];
                #pragma unroll
                for (int g = 0; g < 4; ++g) {
                    a[e][g] = fma2(ev.x, wih[g][c4 * 2 + 0], a[e][g]);
                    a[e][g] = fma2(ev.y, wih[g][c4 * 2 + 1], a[e][g]);
                }
            }
        }

        // merge K halves
        #pragma unroll
        for (int e = 0; e < 4; ++e)
            #pragma unroll
            for (int g = 0; g < 4; ++g)
                a[e][g] = add2(a[e][g], __shfl_xor_sync(0xffffffffu, a[e][g], 16));

        // each half stores its 2 owned elems (coalesced 256B per elem)
        #pragma unroll
        for (int oe = 0; oe < 2; ++oe) {
            const int e = gp * 2 + oe;
            float s[4];
            #pragma unroll
            for (int g = 0; g < 4; ++g) {
                float lo, hi; unpack2(a[e][g], lo, hi);
                s[g] = lo + hi + bias[g];
            }
            g_xproj[((size_t)t * BATCH + (b0w + e)) * HID + j] =
                make_float4(s[0], s[1], s[2], s[3]);
        }
    }
}

// ---------------- Phase B: recurrence ----------------
__global__ __launch_bounds__(CTA_THREADS, 1)
void recur_kernel(const float* __restrict__ w_hh,
                  const float* __restrict__ fc_w,
                  const float* __restrict__ fc_b,
                  float*       __restrict__ out)
{
    __shared__ float h_s[ELEMS_PER_CTA * HID];     // [elem][j]

    const int tid  = threadIdx.x;
    const int warp = tid >> 5, lane = tid & 31;
    const int j    = lane & 15;
    const int gp   = lane >> 4;          // K half: h k in [gp*8, gp*8+8)
    const int we   = warp * 4;
    const int b0w  = blockIdx.x * ELEMS_PER_CTA + we;

    // w_hh rows are 16 consecutive floats -> K-pair u64 loads (32B aligned)
    u64 whh[4][4];
    #pragma unroll
    for (int g = 0; g < 4; ++g) {
        const u64* wr = (const u64*)(w_hh + ((size_t)(g * HID + j) * HID + gp * 8));
        #pragma unroll
        for (int kp = 0; kp < 4; ++kp) whh[g][kp] = wr[kp];
    }

    float ho[2] = {0.f, 0.f}, co[2] = {0.f, 0.f};   // owned elems gp*2, gp*2+1

    float4 xpb[2];
    #pragma unroll
    for (int oe = 0; oe < 2; ++oe)
        xpb[oe] = g_xproj[((size_t)0 * BATCH + (b0w + gp * 2 + oe)) * HID + j];

    const ulonglong2* h_u = (const ulonglong2*)h_s;

    for (int t = 0; t < T_LEN; ++t) {
        __syncwarp();                                   // prior reads done
        h_s[(we + gp * 2 + 0) * HID + j] = ho[0];
        h_s[(we + gp * 2 + 1) * HID + j] = ho[1];
        __syncwarp();                                   // h visible

        const float4 xp0 = xpb[0], xp1 = xpb[1];
        if (t + 1 < T_LEN) {
            #pragma unroll
            for (int oe = 0; oe < 2; ++oe)
                xpb[oe] = g_xproj[((size_t)(t + 1) * BATCH + (b0w + gp * 2 + oe)) * HID + j];
        }

        u64 a[4][4];
        #pragma unroll
        for (int e = 0; e < 4; ++e)
            #pragma unroll
            for (int g = 0; g < 4; ++g) a[e][g] = 0ull;

        // h projection: this half's 8 h values, K-pair packed
        #pragma unroll
        for (int e = 0; e < 4; ++e) {
            const ulonglong2 hv0 = h_u[(we + e) * 4 + gp * 2 + 0];
            const ulonglong2 hv1 = h_u[(we + e) * 4 + gp * 2 + 1];
            #pragma unroll
            for (int g = 0; g < 4; ++g) {
                a[e][g] = fma2(hv0.x, whh[g][0], a[e][g]);
                a[e][g] = fma2(hv0.y, whh[g][1], a[e][g]);
                a[e][g] = fma2(hv1.x, whh[g][2], a[e][g]);
                a[e][g] = fma2(hv1.y, whh[g][3], a[e][g]);
            }
        }

        // merge K halves
        #pragma unroll
        for (int e = 0; e < 4; ++e)
            #pragma unroll
            for (int g = 0; g < 4; ++g)
                a[e][g] = add2(a[e][g], __shfl_xor_sync(0xffffffffu, a[e][g], 16));

        // epilogue only for owned elems (MUFU halved vs R4)
        #pragma unroll
        for (int oe = 0; oe < 2; ++oe) {
            const int e = gp * 2 + oe;
            const float4 xp = oe ? xp1 : xp0;
            float lo, hi, si, sf, sg, so;
            unpack2(a[e][0], lo, hi); si = lo + hi + xp.x;
            unpack2(a[e][1], lo, hi); sf = lo + hi + xp.y;
            unpack2(a[e][2], lo, hi); sg = lo + hi + xp.z;
            unpack2(a[e][3], lo, hi); so = lo + hi + xp.w;
            const float ig = sigf(si), fg = sigf(sf);
            const float gg = tanhf_fast(sg), og = sigf(so);
            co[oe] = fg * co[oe] + ig * gg;
            ho[oe] = og * tanhf_fast(co[oe]);
        }
    }

    // FC head: reduce over j within each half-warp
    const float fcw = fc_w[j];
    const float fcb = fc_b[0];
    #pragma unroll
    for (int oe = 0; oe < 2; ++oe) {
        float v = ho[oe] * fcw;
        v += __shfl_xor_sync(0xffffffffu, v, 8);
        v += __shfl_xor_sync(0xffffffffu, v, 4);
        v += __shfl_xor_sync(0xffffffffu, v, 2);
        v += __shfl_xor_sync(0xffffffffu, v, 1);
        if (j == 0) out[b0w + gp * 2 + oe] = sigf(v + fcb);
    }
}

extern "C" void kernel_launch(void* const* d_in, const int* in_sizes, int n_in,
                              void* d_out, int out_size)
{
    const int*   x     = (const int*)  d_in[0];
    const float* embed = (const float*)d_in[1];
    const float* w_ih  = (const float*)d_in[2];
    const float* w_hh  = (const float*)d_in[3];
    const float* b_ih  = (const float*)d_in[4];
    const float* b_hh  = (const float*)d_in[5];
    const float* fc_w  = (const float*)d_in[6];
    const float* fc_b  = (const float*)d_in[7];
    float* out = (float*)d_out;

    xproj_kernel<<<GRID_CTAS, CTA_THREADS>>>(x, embed, w_ih, b_ih, b_hh);
    recur_kernel<<<GRID_CTAS, CTA_THREADS>>>(w_hh, fc_w, fc_b, out);
}

// round 6
// speedup vs baseline: 1.2910x; 1.2910x over previous
#include <cuda_runtime.h>

// LSTM_46316927320185 — R6: two-phase, barrier-amortized A + high-occupancy shfl B
// B=4096, T=512, EMB=32, HID=16. out = sigmoid(h_T @ fc_w^T + fc_b), [B,1] fp32.
//
// R5 (970us) showed step time invariant to FMA content at 2 warps/SMSP:
// syncwarp-laced short bodies are latency-bound (~1750cyc/step regardless).
// Phase A (xproj, no t-dependency): unroll t by 4 -> 1 syncwarp pair / 4 steps,
//   4 independent bodies (ILP), int4 index loads, 4-deep emb prefetch.
// Phase B (recurrence): warp = 2 elems (lane = 16j x 2eh), full-K per thread,
//   h exchanged via shfl only (NO barriers), K-pair-packed weights loaded as
//   contiguous u64 from gmem rows, xp prefetch depth 2. grid 512 x 128thr ->
//   ~16 warps/SM (4/SMSP) for latency hiding.

#define HID    16
#define EMB    32
#define T_LEN  512
#define BATCH  4096

typedef unsigned long long u64;

// [t][b] -> HID float4s (gates i,f,g,o for unit j), biases folded. 512 MB.
__device__ float4 g_xproj[(size_t)T_LEN * BATCH * HID];

__device__ __forceinline__ u64 fma2(u64 a, u64 b, u64 c) {
    u64 d; asm("fma.rn.f32x2 %0, %1, %2, %3;" : "=l"(d) : "l"(a), "l"(b), "l"(c)); return d;
}
__device__ __forceinline__ u64 add2(u64 a, u64 b) {
    u64 d; asm("add.rn.f32x2 %0, %1, %2;" : "=l"(d) : "l"(a), "l"(b)); return d;
}
__device__ __forceinline__ u64 pack2(float a, float b) {
    u64 r; asm("mov.b64 %0, {%1, %2};" : "=l"(r) : "f"(a), "f"(b)); return r;
}
__device__ __forceinline__ void unpack2(u64 v, float& lo, float& hi) {
    asm("mov.b64 {%0, %1}, %2;" : "=f"(lo), "=f"(hi) : "l"(v));
}
__device__ __forceinline__ float hadd2(u64 v) {
    float lo, hi; unpack2(v, lo, hi); return lo + hi;
}
__device__ __forceinline__ float sigf(float x) {
    return __fdividef(1.0f, 1.0f + __expf(-x));
}
__device__ __forceinline__ float tanhf_fast(float x) {
    return __fdividef(2.0f, 1.0f + __expf(-2.0f * x)) - 1.0f;
}

// ================= Phase A: input projection, t unrolled by 4 =================
#define A_ELEMS   32
#define A_THREADS 256
#define A_GRID    (BATCH / A_ELEMS)    // 128

__global__ __launch_bounds__(A_THREADS, 1)
void xproj_kernel(const int*   __restrict__ x,
                  const float* __restrict__ embed,
                  const float* __restrict__ w_ih,
                  const float* __restrict__ b_ih,
                  const float* __restrict__ b_hh)
{
    // [elem][ts(4)][chunk(8)] float4 staging, 16 KB
    __shared__ float4 emb_s4[A_ELEMS * 4 * 8];

    const int tid  = threadIdx.x;
    const int warp = tid >> 5, lane = tid & 31;
    const int j    = lane & 15;          // hidden unit
    const int gp   = lane >> 4;          // emb K half: [gp*16, gp*16+16)
    const int we   = warp * 4;
    const int b0w  = blockIdx.x * A_ELEMS + we;

    // w_ih rows contiguous -> K-pair u64 loads for this half
    u64 wih[4][8];
    #pragma unroll
    for (int g = 0; g < 4; ++g) {
        const u64* wr = (const u64*)(w_ih + ((size_t)(g * HID + j) * EMB + gp * 16));
        #pragma unroll
        for (int kp = 0; kp < 8; ++kp) wih[g][kp] = wr[kp];
    }
    float bias[4];
    #pragma unroll
    for (int g = 0; g < 4; ++g) bias[g] = b_ih[g * HID + j] + b_hh[g * HID + j];

    const int pe = lane >> 3, chunk = lane & 7;   // gather: lane -> (elem, chunk)
    const int* xcol = x + (long)(b0w + pe) * T_LEN;

    int4 xi = *(const int4*)xcol;
    float4 pre[4];
    pre[0] = ((const float4*)(embed + (size_t)xi.x * EMB))[chunk];
    pre[1] = ((const float4*)(embed + (size_t)xi.y * EMB))[chunk];
    pre[2] = ((const float4*)(embed + (size_t)xi.z * EMB))[chunk];
    pre[3] = ((const float4*)(embed + (size_t)xi.w * EMB))[chunk];

    const ulonglong2* emb_u = (const ulonglong2*)emb_s4;

    for (int tb = 0; tb < T_LEN / 4; ++tb) {
        __syncwarp();
        #pragma unroll
        for (int ts = 0; ts < 4; ++ts)
            emb_s4[((we + pe) * 4 + ts) * 8 + chunk] = pre[ts];
        __syncwarp();

        if (tb + 1 < T_LEN / 4) {
            xi = *(const int4*)(xcol + (tb + 1) * 4);
            pre[0] = ((const float4*)(embed + (size_t)xi.x * EMB))[chunk];
            pre[1] = ((const float4*)(embed + (size_t)xi.y * EMB))[chunk];
            pre[2] = ((const float4*)(embed + (size_t)xi.z * EMB))[chunk];
            pre[3] = ((const float4*)(embed + (size_t)xi.w * EMB))[chunk];
        }

        #pragma unroll
        for (int ts = 0; ts < 4; ++ts) {
            const int t = tb * 4 + ts;
            u64 a[4][4];
            #pragma unroll
            for (int e = 0; e < 4; ++e)
                #pragma unroll
                for (int g = 0; g < 4; ++g) a[e][g] = 0ull;

            #pragma unroll
            for (int e = 0; e < 4; ++e) {
                #pragma unroll
                for (int c4 = 0; c4 < 4; ++c4) {
                    const ulonglong2 ev = emb_u[((we + e) * 4 + ts) * 8 + gp * 4 + c4];
                    #pragma unroll
                    for (int g = 0; g < 4; ++g) {
                        a[e][g] = fma2(ev.x, wih[g][c4 * 2 + 0], a[e][g]);
                        a[e][g] = fma2(ev.y, wih[g][c4 * 2 + 1], a[e][g]);
                    }
                }
            }
            // merge K halves
            #pragma unroll
            for (int e = 0; e < 4; ++e)
                #pragma unroll
                for (int g = 0; g < 4; ++g)
                    a[e][g] = add2(a[e][g], __shfl_xor_sync(0xffffffffu, a[e][g], 16));

            // each half stores its 2 owned elems (256B coalesced per elem)
            #pragma unroll
            for (int oe = 0; oe < 2; ++oe) {
                const int e = gp * 2 + oe;
                float s[4];
                #pragma unroll
                for (int g = 0; g < 4; ++g) s[g] = hadd2(a[e][g]) + bias[g];
                g_xproj[((size_t)t * BATCH + (b0w + e)) * HID + j] =
                    make_float4(s[0], s[1], s[2], s[3]);
            }
        }
    }
}

// ================= Phase B: recurrence, shfl-only, 2 elems/warp =================
#define B_THREADS 128
#define B_ELEMS   8                     // 4 warps x 2 elems
#define B_GRID    (BATCH / B_ELEMS)     // 512

__global__ __launch_bounds__(B_THREADS)
void recur_kernel(const float* __restrict__ w_hh,
                  const float* __restrict__ fc_w,
                  const float* __restrict__ fc_b,
                  float*       __restrict__ out)
{
    const int tid  = threadIdx.x;
    const int warp = tid >> 5, lane = tid & 31;
    const int eh   = lane >> 4;          // which of the warp's 2 elems
    const int j    = lane & 15;          // hidden unit
    const int b    = blockIdx.x * B_ELEMS + warp * 2 + eh;
    const int base = eh * 16;            // shfl source base for this elem

    // K-pair packed weights, contiguous u64 loads: wk[g][i] = (w[g,j,2i], w[g,j,2i+1])
    u64 wk[4][8];
    #pragma unroll
    for (int g = 0; g < 4; ++g) {
        const u64* wr = (const u64*)(w_hh + (size_t)(g * HID + j) * HID);
        #pragma unroll
        for (int i = 0; i < 8; ++i) wk[g][i] = wr[i];
    }

    float h = 0.f, c = 0.f;

    // xp stream, prefetch depth 2
    float4 xc = g_xproj[((size_t)0 * BATCH + b) * HID + j];
    float4 xn = g_xproj[((size_t)1 * BATCH + b) * HID + j];

    for (int t = 0; t < T_LEN; ++t) {
        // gather h pairs of this elem via shfl (warp-synchronous, no barriers)
        u64 a0 = 0ull, a1 = 0ull, a2 = 0ull, a3 = 0ull;
        #pragma unroll
        for (int i = 0; i < 8; ++i) {
            const float hlo = __shfl_sync(0xffffffffu, h, base + 2 * i);
            const float hhi = __shfl_sync(0xffffffffu, h, base + 2 * i + 1);
            const u64 hp = pack2(hlo, hhi);
            a0 = fma2(hp, wk[0][i], a0);
            a1 = fma2(hp, wk[1][i], a1);
            a2 = fma2(hp, wk[2][i], a2);
            a3 = fma2(hp, wk[3][i], a3);
        }

        const float si = hadd2(a0) + xc.x;
        const float sf = hadd2(a1) + xc.y;
        const float sg = hadd2(a2) + xc.z;
        const float so = hadd2(a3) + xc.w;

        xc = xn;
        if (t + 2 < T_LEN)
            xn = g_xproj[((size_t)(t + 2) * BATCH + b) * HID + j];

        const float ig = sigf(si), fg = sigf(sf);
        const float gg = tanhf_fast(sg), og = sigf(so);
        c = fg * c + ig * gg;
        h = og * tanhf_fast(c);
    }

    // FC head: reduce over j within this elem's 16-lane half
    float v = h * fc_w[j];
    v += __shfl_xor_sync(0xffffffffu, v, 8);
    v += __shfl_xor_sync(0xffffffffu, v, 4);
    v += __shfl_xor_sync(0xffffffffu, v, 2);
    v += __shfl_xor_sync(0xffffffffu, v, 1);
    if (j == 0) out[b] = sigf(v + fc_b[0]);
}

extern "C" void kernel_launch(void* const* d_in, const int* in_sizes, int n_in,
                              void* d_out, int out_size)
{
    const int*   x     = (const int*)  d_in[0];
    const float* embed = (const float*)d_in[1];
    const float* w_ih  = (const float*)d_in[2];
    const float* w_hh  = (const float*)d_in[3];
    const float* b_ih  = (const float*)d_in[4];
    const float* b_hh  = (const float*)d_in[5];
    const float* fc_w  = (const float*)d_in[6];
    const float* fc_b  = (const float*)d_in[7];
    float* out = (float*)d_out;

    xproj_kernel<<<A_GRID, A_THREADS>>>(x, embed, w_ih, b_ih, b_hh);
    recur_kernel<<<B_GRID, B_THREADS>>>(w_hh, fc_w, fc_b, out);
}

// round 7
// speedup vs baseline: 4.8331x; 3.7438x over previous
#include <cuda_runtime.h>

// LSTM_46316927320185 — R7: vocab-projection table + lean tanh.approx recurrence
// B=4096, T=512, EMB=32, HID=16, VOCAB=50000.
//
// Key insight: xp[b][t] = w_ih@emb[x[b,t]] + biases depends ONLY on the vocab
// id. 2.1M token instances vs 50K vocab rows = 40x redundancy. Precompute
// tbl[v][j] = float4 gate preactivations (102M FMA, ~15us, 12.8MB -> L2) and
// gather 256B rows in the recurrence. Kills R6's 485us xproj phase AND the
// 512MB DRAM scratch round-trip.
// Recurrence upgrades vs R6 (266us): barrier-free double-buffered smem h
// exchange (h-pairs land as ready u64 fma2 operands, replaces 16 shfl+8 mov),
// tanh.approx.f32 activations (5 MUFU vs ~40-instr exp/div chains), 2-deep
// table prefetch with indices 3 ahead.

#define HID    16
#define EMB    32
#define T_LEN  512
#define BATCH  4096
#define VOCAB  50000

typedef unsigned long long u64;

// [v*HID + j] -> float4 (xp_i, xp_f, xp_g, xp_o) with b_ih+b_hh folded. 12.8 MB.
__device__ float4 g_tbl[(size_t)VOCAB * HID];

__device__ __forceinline__ u64 fma2(u64 a, u64 b, u64 c) {
    u64 d; asm("fma.rn.f32x2 %0, %1, %2, %3;" : "=l"(d) : "l"(a), "l"(b), "l"(c)); return d;
}
__device__ __forceinline__ u64 rep2(float v) {
    u64 r; asm("mov.b64 %0, {%1, %1};" : "=l"(r) : "f"(v)); return r;
}
__device__ __forceinline__ void unpack2(u64 v, float& lo, float& hi) {
    asm("mov.b64 {%0, %1}, %2;" : "=f"(lo), "=f"(hi) : "l"(v));
}
__device__ __forceinline__ float hadd2(u64 v) {
    float lo, hi; unpack2(v, lo, hi); return lo + hi;
}
__device__ __forceinline__ float tanh_ap(float x) {
    float y; asm("tanh.approx.f32 %0, %1;" : "=f"(y) : "f"(x)); return y;
}
__device__ __forceinline__ float sig_ap(float x) {
    return fmaf(tanh_ap(0.5f * x), 0.5f, 0.5f);
}

// ============ Phase A: per-vocab projection table ============
#define PT_THREADS 256
#define PT_GRID    ((VOCAB * HID) / PT_THREADS)   // 3125

__global__ __launch_bounds__(PT_THREADS)
void proj_table_kernel(const float* __restrict__ embed,
                       const float* __restrict__ w_ih,
                       const float* __restrict__ b_ih,
                       const float* __restrict__ b_hh)
{
    // gate-packed transposed weights: [k*HID+j] = ((wi,wf),(wg,wo))
    __shared__ ulonglong2 w_u[EMB * HID];   // 8 KB

    const int tid = threadIdx.x;
    for (int i = tid; i < EMB * HID; i += PT_THREADS) {
        int k = i / HID, jj = i % HID;
        float4 w = make_float4(w_ih[(0 * HID + jj) * EMB + k],
                               w_ih[(1 * HID + jj) * EMB + k],
                               w_ih[(2 * HID + jj) * EMB + k],
                               w_ih[(3 * HID + jj) * EMB + k]);
        *(float4*)&w_u[i] = w;
    }
    __syncthreads();

    const int gid = blockIdx.x * PT_THREADS + tid;
    const int v = gid >> 4;        // vocab row
    const int j = gid & 15;        // hidden unit

    const float* er = embed + (size_t)v * EMB;
    u64 a01 = 0ull, a23 = 0ull;
    #pragma unroll
    for (int k = 0; k < EMB; ++k) {
        const u64 q = rep2(er[k]);              // broadcast across 16 j-lanes
        const ulonglong2 w = w_u[k * HID + j];
        a01 = fma2(q, w.x, a01);
        a23 = fma2(q, w.y, a23);
    }
    float ai, af, ag, ao;
    unpack2(a01, ai, af);
    unpack2(a23, ag, ao);
    g_tbl[gid] = make_float4(ai + b_ih[j]           + b_hh[j],
                             af + b_ih[HID + j]     + b_hh[HID + j],
                             ag + b_ih[2 * HID + j] + b_hh[2 * HID + j],
                             ao + b_ih[3 * HID + j] + b_hh[3 * HID + j]);
}

// ============ Phase B: recurrence (2 elems/warp, smem h-exchange) ============
#define B_THREADS 128
#define B_WARPS   4
#define B_ELEMS   8                     // 2 per warp
#define B_GRID    (BATCH / B_ELEMS)     // 512

__global__ __launch_bounds__(B_THREADS)
void recur_kernel(const int*   __restrict__ x,
                  const float* __restrict__ w_hh,
                  const float* __restrict__ fc_w,
                  const float* __restrict__ fc_b,
                  float*       __restrict__ out)
{
    // double-buffered h staging: [buf][warp][elem][j] (pairs contiguous -> u64)
    __shared__ float h_s[2][B_WARPS][2][HID];

    const int tid  = threadIdx.x;
    const int warp = tid >> 5, lane = tid & 31;
    const int eh   = lane >> 4;          // which of the warp's 2 elems
    const int j    = lane & 15;          // hidden unit
    const int b    = blockIdx.x * B_ELEMS + warp * 2 + eh;

    // K-pair packed recurrent weights: wk[g][i] = (w[g,j,2i], w[g,j,2i+1])
    u64 wk[4][8];
    #pragma unroll
    for (int g = 0; g < 4; ++g) {
        const u64* wr = (const u64*)(w_hh + (size_t)(g * HID + j) * HID);
        #pragma unroll
        for (int i = 0; i < 8; ++i) wk[g][i] = wr[i];
    }

    const int* xcol = x + (size_t)b * T_LEN;

    // gather pipeline: xp for t (xc), t+1 (xn); index for t+2 (i2)
    float4 xc = g_tbl[(size_t)xcol[0] * HID + j];
    float4 xn = g_tbl[(size_t)xcol[1] * HID + j];
    int    i2 = xcol[2];

    float h = 0.f, c = 0.f;

    #pragma unroll 4
    for (int t = 0; t < T_LEN; ++t) {
        const int buf = t & 1;
        h_s[buf][warp][eh][j] = h;
        __syncwarp();

        // kick next gathers early (t+2 row; t+3 index)
        const float4 x2 = g_tbl[(size_t)i2 * HID + j];
        const int    i3 = xcol[(t + 3 < T_LEN) ? (t + 3) : (T_LEN - 1)];

        const ulonglong2* hp = (const ulonglong2*)h_s[buf][warp][eh];
        u64 a0 = 0ull, a1 = 0ull, a2 = 0ull, a3 = 0ull;
        #pragma unroll
        for (int i = 0; i < 4; ++i) {
            const ulonglong2 hv = hp[i];   // ((h2i,h2i+1),(h2i+2,h2i+3)) ready-packed
            a0 = fma2(hv.x, wk[0][2 * i], a0); a0 = fma2(hv.y, wk[0][2 * i + 1], a0);
            a1 = fma2(hv.x, wk[1][2 * i], a1); a1 = fma2(hv.y, wk[1][2 * i + 1], a1);
            a2 = fma2(hv.x, wk[2][2 * i], a2); a2 = fma2(hv.y, wk[2][2 * i + 1], a2);
            a3 = fma2(hv.x, wk[3][2 * i], a3); a3 = fma2(hv.y, wk[3][2 * i + 1], a3);
        }

        const float si = hadd2(a0) + xc.x;
        const float sf = hadd2(a1) + xc.y;
        const float sg = hadd2(a2) + xc.z;
        const float so = hadd2(a3) + xc.w;

        xc = xn; xn = x2; i2 = i3;

        const float ig = sig_ap(si), fg = sig_ap(sf);
        const float gg = tanh_ap(sg), og = sig_ap(so);
        c = fg * c + ig * gg;
        h = og * tanh_ap(c);
    }

    // FC head: reduce over j within this elem's 16-lane half
    float v = h * fc_w[j];
    v += __shfl_xor_sync(0xffffffffu, v, 8);
    v += __shfl_xor_sync(0xffffffffu, v, 4);
    v += __shfl_xor_sync(0xffffffffu, v, 2);
    v += __shfl_xor_sync(0xffffffffu, v, 1);
    if (j == 0) out[b] = sig_ap(v + fc_b[0]);
}

extern "C" void kernel_launch(void* const* d_in, const int* in_sizes, int n_in,
                              void* d_out, int out_size)
{
    const int*   x     = (const int*)  d_in[0];
    const float* embed = (const float*)d_in[1];
    const float* w_ih  = (const float*)d_in[2];
    const float* w_hh  = (const float*)d_in[3];
    const float* b_ih  = (const float*)d_in[4];
    const float* b_hh  = (const float*)d_in[5];
    const float* fc_w  = (const float*)d_in[6];
    const float* fc_b  = (const float*)d_in[7];
    float* out = (float*)d_out;

    proj_table_kernel<<<PT_GRID, PT_THREADS>>>(embed, w_ih, b_ih, b_hh);
    recur_kernel<<<B_GRID, B_THREADS>>>(x, w_hh, fc_w, fc_b, out);
}